// round 11
// baseline (speedup 1.0000x reference)
#include <cuda_runtime.h>
#include <cuda_bf16.h>
#include <cstdint>

#define D        1024
#define NBLK     6
#define NV       7            // 6 blocks + partial
#define THREADS  512
#define NWARP    16
#define REPS     1e-6f
#define INV_SCALE (1.0f/32.0f)   // 1/(sqrt(1024)*temperature)
#define GRID     444             // 3 CTAs/SM x 148 SMs, one exact wave

// dynamic smem layout (floats):
//   buf   : [2][NV][THREADS] float2   = 14336 floats (57344 B)
//   s_red : [NWARP][16]               =   256 floats
//   s_sc  : [8]                       =     8 floats
//   s_coef: [8] (16B aligned)         =     8 floats
#define BUF_FLOATS   (2 * NV * THREADS * 2)
#define SMEM_FLOATS  (BUF_FLOATS + NWARP * 16 + 8 + 8)
#define SMEM_BYTES   (SMEM_FLOATS * 4)

__global__ void __launch_bounds__(THREADS, 3)
reskip_kernel(const float* __restrict__ blocks,
              const float* __restrict__ partial,
              const float* __restrict__ w_query,
              const float* __restrict__ norm_w,
              float* __restrict__ out,
              int bt, long long blk_stride)
{
    extern __shared__ __align__(16) float smem[];
    float2* buf    = reinterpret_cast<float2*>(smem);      // [2][NV][THREADS]
    float*  s_red  = smem + BUF_FLOATS;                    // [NWARP][16]
    float*  s_sc   = s_red + NWARP * 16;                   // [8]
    float*  s_coef = s_sc + 8;                             // [8], 16B aligned

    const int tid  = threadIdx.x;
    const int warp = tid >> 5, lane = tid & 31;
    const int j    = tid * 2;                   // this thread's 2 channels
    const int stride = gridDim.x;

    // effective query = w_query * norm_weight (fp32)
    float2 q2  = *(const float2*)(w_query + j);
    float2 nw2 = *(const float2*)(norm_w  + j);
    const float q0 = q2.x * nw2.x, q1 = q2.y * nw2.y;

    int tok = blockIdx.x;
    if (tok >= bt) return;

    // ---- prologue: prefetch first token into buffer 0 via cp.async
    {
        const long long base = (long long)tok * D + j;
        #pragma unroll
        for (int n = 0; n < NV; n++) {
            const float* g = (n < NBLK)
                ? (blocks + (long long)n * blk_stride + base)
                : (partial + base);
            uint32_t sa = (uint32_t)__cvta_generic_to_shared(
                              buf + (0 * NV + n) * THREADS + tid);
            asm volatile("cp.async.ca.shared.global [%0], [%1], 8;"
                         :: "r"(sa), "l"(g));
        }
        asm volatile("cp.async.commit_group;" ::: "memory");
    }

    int p = 0;
    while (tok < bt) {
        const int ntok = tok + stride;
        const long long base = (long long)tok * D + j;

        // wait for this iteration's buffer (self-written; no barrier needed)
        asm volatile("cp.async.wait_group 0;" ::: "memory");

        // ---- score partials from smem buffer p
        //   v[0..6] = q.x per vector, v[7..13] = x.x, v[14..15] = pad
        float v[16];
        #pragma unroll
        for (int n = 0; n < NV; n++) {
            float2 d = buf[(p * NV + n) * THREADS + tid];
            v[n]     = fmaf(q1, d.y, q0 * d.x);
            v[n + 7] = fmaf(d.y, d.y, d.x * d.x);
        }
        v[14] = 0.f; v[15] = 0.f;

        // ---- prefetch next token into the other buffer NOW; its DRAM
        // latency hides under the reduction/barriers/epilogue below.
        {
            const long long nbase =
                (long long)(ntok < bt ? ntok : tok) * D + j;  // safe addr on tail
            #pragma unroll
            for (int n = 0; n < NV; n++) {
                const float* g = (n < NBLK)
                    ? (blocks + (long long)n * blk_stride + nbase)
                    : (partial + nbase);
                uint32_t sa = (uint32_t)__cvta_generic_to_shared(
                                  buf + ((p ^ 1) * NV + n) * THREADS + tid);
                asm volatile("cp.async.ca.shared.global [%0], [%1], 8;"
                             :: "r"(sa), "l"(g));
            }
            asm volatile("cp.async.commit_group;" ::: "memory");
        }

        // ---- value-specializing butterfly: 16 values, 16 SHFL total.
        // Final: lane l holds the full-warp sum of value (l >> 1).
        #pragma unroll
        for (int off = 16, k = 8; off >= 2; off >>= 1, k >>= 1) {
            #pragma unroll
            for (int i = 0; i < 8; i++) {
                if (i < k) {
                    float send = (lane & off) ? v[i] : v[i + k];
                    float recv = __shfl_xor_sync(0xffffffffu, send, off);
                    v[i] = ((lane & off) ? v[i + k] : v[i]) + recv;
                }
            }
        }
        v[0] += __shfl_xor_sync(0xffffffffu, v[0], 1);

        if (!(lane & 1) && (lane >> 1) < 14)
            s_red[warp * 16 + (lane >> 1)] = v[0];
        __syncthreads();

        if (warp == 0) {
            float t = 0.f;
            if (lane < 14) {
                #pragma unroll
                for (int w = 0; w < NWARP; w++) t += s_red[w * 16 + lane];
            }
            float xxv = __shfl_sync(0xffffffffu, t, (lane + 7) & 31);
            if (lane < NV) {
                float inv = rsqrtf(xxv * (1.0f / (float)D) + REPS);
                s_sc[lane] = t * inv * INV_SCALE;
            }
            __syncwarp();

            if (lane == 0) {
                float sc[NV];
                #pragma unroll
                for (int n = 0; n < NV; n++) sc[n] = s_sc[n];

                // Phase-1 softmax over the 6 completed blocks
                float m1 = sc[0];
                #pragma unroll
                for (int n = 1; n < NBLK; n++) m1 = fmaxf(m1, sc[n]);
                float es[NBLK], lse = 0.f;
                #pragma unroll
                for (int n = 0; n < NBLK; n++) { es[n] = expf(sc[n] - m1); lse += es[n]; }
                float logl = logf(lse);
                float ent1 = 0.f;
                #pragma unroll
                for (int n = 0; n < NBLK; n++)
                    ent1 -= (es[n] / lse) * ((sc[n] - m1) - logl);

                // Online-softmax merge with partial block
                float ps    = sc[6];
                float mm    = fmaxf(m1, ps);
                float c1    = expf(m1 - mm);
                float cp    = expf(ps - mm);
                float denom = c1 * lse + cp;
                float w1w   = c1 * lse / denom;     // phase1_weight
                float pw    = cp / denom;           // partial_weight

                #pragma unroll
                for (int n = 0; n < NBLK; n++) s_coef[n] = w1w * es[n];
                s_coef[6] = pw;
                s_coef[7] = 0.f;

                float w1c = fmaxf(w1w, 1e-8f);
                float wpc = fmaxf(pw,  1e-8f);
                out[(long long)bt * D + tok] =
                    w1c * ent1 - w1c * logf(w1c) - wpc * logf(wpc);
            }
        }
        __syncthreads();

        // ---- epilogue: coefficients via 2 vector LDS, data re-read from buf[p]
        float4 cA = *(const float4*)&s_coef[0];
        float4 cB = *(const float4*)&s_coef[4];
        const float cc[NV] = { cA.x, cA.y, cA.z, cA.w, cB.x, cB.y, cB.z };

        float o0 = 0.f, o1 = 0.f;
        #pragma unroll
        for (int n = 0; n < NV; n++) {
            float2 d = buf[(p * NV + n) * THREADS + tid];
            o0 = fmaf(cc[n], d.x, o0);
            o1 = fmaf(cc[n], d.y, o1);
        }
        *(float2*)(out + base) = make_float2(o0, o1);

        p ^= 1;
        tok = ntok;
    }
}

extern "C" void kernel_launch(void* const* d_in, const int* in_sizes, int n_in,
                              void* d_out, int out_size)
{
    const float* blocks  = (const float*)d_in[0];   // [6, b, t, d]
    const float* partial = (const float*)d_in[1];   // [b, t, d]
    const float* wq      = (const float*)d_in[2];   // [d]
    const float* nw      = (const float*)d_in[3];   // [d]
    float* out           = (float*)d_out;           // [b*t*d hidden][b*t entropy]

    int bt = in_sizes[1] / D;                       // b*t tokens
    long long blk_stride = (long long)in_sizes[0] / NBLK;  // b*t*d

    cudaFuncSetAttribute(reskip_kernel,
                         cudaFuncAttributeMaxDynamicSharedMemorySize, SMEM_BYTES);

    int grid = GRID < bt ? GRID : bt;
    reskip_kernel<<<grid, THREADS, SMEM_BYTES>>>(blocks, partial, wq, nw, out,
                                                 bt, blk_stride);
}